// round 2
// baseline (speedup 1.0000x reference)
#include <cuda_runtime.h>
#include <stdint.h>

// Problem constants
#define BB 32
#define NN 1024
#define DD 768
#define D4 (DD/4)          // 192 float4 per row
#define KMASK 768          // masked tokens per row
#define NUNM  256          // unmasked tokens per row
#define TOK_PER_BLK 8

// Output layout (float32 concat of the 5 reference outputs, flattened in order)
#define OFF_WITHMASK 0ull
#define OFF_UNMP   ((unsigned long long)BB*NN*DD)                       // 25165824
#define OFF_BOOL   (OFF_UNMP + (unsigned long long)BB*NUNM*DD)          // 31457280
#define OFF_MIDX   (OFF_BOOL + (unsigned long long)BB*NN*DD)            // 56623104
#define OFF_UIDX   (OFF_MIDX + (unsigned long long)BB*KMASK)            // 56647680

// Scratch
__device__ int g_bool[BB * NN];   // bool_mask by position t
__device__ int g_info[BB * NN];   // -1 => masked; else rank among unmasked

// ---------------------------------------------------------------------------
// Kernel A: distributed rank-by-counting.
// Grid (8, 32): chunk c, batch b. 128 threads, each owns one element i and
// counts how many of the 1024 keys are smaller. key = (float_bits<<10)|index
// gives exact stable-argsort semantics (index tiebreak). Ranks form a
// permutation, so g_bool[b][rank_i] is written exactly once per slot.
// ---------------------------------------------------------------------------
__global__ __launch_bounds__(128, 8)
void rank_kernel(const float* __restrict__ noise)
{
    __shared__ __align__(16) unsigned long long s_key[NN];

    const int c = blockIdx.x;
    const int b = blockIdx.y;
    const int tid = threadIdx.x;

    #pragma unroll
    for (int r = 0; r < NN / 128; ++r) {
        int j = r * 128 + tid;
        float v = noise[b * NN + j];
        s_key[j] = ((unsigned long long)__float_as_uint(v) << 10) | (unsigned)j;
    }
    __syncthreads();

    const int i = c * 128 + tid;
    const unsigned long long ki = s_key[i];
    int cnt = 0;
    #pragma unroll 4
    for (int j = 0; j < NN; j += 2) {
        ulonglong2 k2 = *reinterpret_cast<const ulonglong2*>(&s_key[j]);
        cnt += (k2.x < ki) + (k2.y < ki);
    }
    // bool_mask[rank_i] = (perm[rank_i] < KMASK) = (i < KMASK)
    g_bool[b * NN + cnt] = (i < KMASK) ? 1 : 0;
}

// ---------------------------------------------------------------------------
// Kernel B: finalize. 32 blocks x 1024 threads: ballot prefix scan of the
// mask, emit masked/unmasked index outputs (as float) and per-token info.
// ---------------------------------------------------------------------------
__global__ __launch_bounds__(1024, 1)
void finalize_kernel(float* __restrict__ out)
{
    __shared__ int warp_sums[32];

    const int b = blockIdx.x;
    const int t = threadIdx.x;
    const int lane = t & 31;
    const int warp = t >> 5;

    int m = g_bool[b * NN + t];

    unsigned ballot = __ballot_sync(0xFFFFFFFFu, m);
    int before_in_warp = __popc(ballot & ((1u << lane) - 1u));
    if (lane == 0) warp_sums[warp] = __popc(ballot);
    __syncthreads();
    int warp_before = 0;
    #pragma unroll
    for (int w = 0; w < 32; ++w)
        warp_before += (w < warp) ? warp_sums[w] : 0;
    int t_before = warp_before + before_in_warp;

    float* masked_out = out + OFF_MIDX;
    float* unm_out    = out + OFF_UIDX;
    if (m) {
        masked_out[b * KMASK + t_before] = (float)t;
        g_info[b * NN + t] = -1;
    } else {
        int r = t - t_before;
        unm_out[b * NUNM + r] = (float)t;
        g_info[b * NN + t] = r;
    }
}

// ---------------------------------------------------------------------------
// Kernel C: scatter, 8 tokens per block (4096 blocks x 192 thr).
// Prefetch all 8 infos (MLP), hoist mask_emb float4 into a register once,
// unrolled per-token loop: bool row (const), with_mask row, and for unmasked
// tokens scatter the single patch read into unmasked_patches_only too.
// ---------------------------------------------------------------------------
__global__ __launch_bounds__(192, 8)
void mask_scatter_kernel(const float* __restrict__ patch,
                         const float* __restrict__ mask_emb,
                         float* __restrict__ out)
{
    const int tok0 = blockIdx.x * TOK_PER_BLK;
    const int b    = tok0 >> 10;           // 8 | 1024, so one batch per block
    const int t    = threadIdx.x;          // float4 lane 0..191

    // Per-block invariants
    const float4 me = __ldg(reinterpret_cast<const float4*>(mask_emb) + t);

    int infos[TOK_PER_BLK];
    #pragma unroll
    for (int it = 0; it < TOK_PER_BLK; ++it)
        infos[it] = __ldg(&g_info[tok0 + it]);

    float4* wm_base = reinterpret_cast<float4*>(out + OFF_WITHMASK);
    float4* be_base = reinterpret_cast<float4*>(out + OFF_BOOL);
    float4* up_base = reinterpret_cast<float4*>(out + OFF_UNMP);
    const float4* patch4 = reinterpret_cast<const float4*>(patch);

    #pragma unroll
    for (int it = 0; it < TOK_PER_BLK; ++it) {
        const int tok = tok0 + it;
        const int info = infos[it];
        const size_t row = (size_t)tok * D4;

        const float bv = (info < 0) ? 1.0f : 0.0f;
        be_base[row + t] = make_float4(bv, bv, bv, bv);

        if (info < 0) {
            wm_base[row + t] = me;
        } else {
            float4 p = __ldg(patch4 + row + t);
            wm_base[row + t] = p;
            up_base[((size_t)b * NUNM + info) * D4 + t] = p;
        }
    }
}

extern "C" void kernel_launch(void* const* d_in, const int* in_sizes, int n_in,
                              void* d_out, int out_size)
{
    const float* patch    = (const float*)d_in[0];  // (B, N, D) f32
    const float* noise    = (const float*)d_in[1];  // (B, N)    f32
    const float* mask_emb = (const float*)d_in[2];  // (D,)      f32
    float* out = (float*)d_out;

    rank_kernel<<<dim3(NN / 128, BB), 128>>>(noise);
    finalize_kernel<<<BB, 1024>>>(out);
    mask_scatter_kernel<<<BB * NN / TOK_PER_BLK, 192>>>(patch, mask_emb, out);
}

// round 3
// speedup vs baseline: 1.0572x; 1.0572x over previous
#include <cuda_runtime.h>
#include <stdint.h>

// Problem constants
#define BB 32
#define NN 1024
#define DD 768
#define D4 (DD/4)          // 192 float4 per row
#define KMASK 768          // masked tokens per row
#define NUNM  256          // unmasked tokens per row
#define TOK_PER_BLK 8

// Output layout (float32 concat of the 5 reference outputs, flattened in order)
#define OFF_WITHMASK 0ull
#define OFF_UNMP   ((unsigned long long)BB*NN*DD)                       // 25165824
#define OFF_BOOL   (OFF_UNMP + (unsigned long long)BB*NUNM*DD)          // 31457280
#define OFF_MIDX   (OFF_BOOL + (unsigned long long)BB*NN*DD)            // 56623104
#define OFF_UIDX   (OFF_MIDX + (unsigned long long)BB*KMASK)            // 56647680

// Scratch: per-token info. -1 => masked; else rank among unmasked (0..255)
__device__ int g_info[BB * NN];

// ---------------------------------------------------------------------------
// Kernel 1: hybrid register/shuffle bitonic argsort + fused finalize.
// One block of 1024 threads per batch row; element t lives in a register.
// Stages with partner distance j<32 use __shfl_xor (40 of 55 stages, no
// barrier); j>=32 stages use double-buffered smem (1 barrier each, 15 total).
// key = (float_bits << 32) | index: positive uniform floats sort by bit
// pattern, index tiebreak == stable argsort (matches jnp.argsort).
// ---------------------------------------------------------------------------
__global__ __launch_bounds__(1024, 1)
void mask_sort_kernel(const float* __restrict__ noise, float* __restrict__ out)
{
    __shared__ unsigned long long sbuf[2][NN];
    __shared__ int warp_sums[32];

    const int b = blockIdx.x;
    const int t = threadIdx.x;

    float v = noise[b * NN + t];
    unsigned long long key =
        ((unsigned long long)__float_as_uint(v) << 32) | (unsigned)t;

    int p = 0;
    #pragma unroll 1
    for (int k = 2; k <= NN; k <<= 1) {
        const bool up = ((t & k) == 0);
        #pragma unroll 1
        for (int j = k >> 1; j > 0; j >>= 1) {
            unsigned long long other;
            if (j >= 32) {
                sbuf[p][t] = key;
                __syncthreads();
                other = sbuf[p][t ^ j];
                p ^= 1;
            } else {
                other = __shfl_xor_sync(0xFFFFFFFFu, key, j);
            }
            const bool lower = ((t & j) == 0);
            const bool keep_small = (up == lower);
            const bool take = keep_small ? (other < key) : (other > key);
            if (take) key = other;
        }
    }

    // key now = t-th smallest; perm[t] = its original index
    int perm = (int)(key & 0xFFFFFFFFu);
    int m = (perm < KMASK) ? 1 : 0;   // bool_mask at position t

    // Exclusive prefix sum of m (ballot + warp sums)
    const int lane = t & 31;
    const int warp = t >> 5;
    unsigned ballot = __ballot_sync(0xFFFFFFFFu, m);
    int before_in_warp = __popc(ballot & ((1u << lane) - 1u));
    if (lane == 0) warp_sums[warp] = __popc(ballot);
    __syncthreads();
    int warp_before = 0;
    #pragma unroll
    for (int w = 0; w < 32; ++w)
        warp_before += (w < warp) ? warp_sums[w] : 0;
    int t_before = warp_before + before_in_warp;   // # Trues at positions < t

    // order = stable argsort(bool_mask): False positions first, then True.
    float* masked_out = out + OFF_MIDX;
    float* unm_out    = out + OFF_UIDX;
    if (m) {
        masked_out[b * KMASK + t_before] = (float)t;
        g_info[b * NN + t] = -1;
    } else {
        int r = t - t_before;                      // rank among unmasked
        unm_out[b * NUNM + r] = (float)t;
        g_info[b * NN + t] = r;
    }
}

// ---------------------------------------------------------------------------
// Kernel 2: scatter, 8 tokens per block (4096 blocks x 192 thr).
// Prefetch all 8 infos (MLP), hoist mask_emb float4 into a register once,
// unrolled per-token loop: bool row (const), with_mask row, and for unmasked
// tokens scatter the single patch read into unmasked_patches_only too.
// ---------------------------------------------------------------------------
__global__ __launch_bounds__(192, 8)
void mask_scatter_kernel(const float* __restrict__ patch,
                         const float* __restrict__ mask_emb,
                         float* __restrict__ out)
{
    const int tok0 = blockIdx.x * TOK_PER_BLK;
    const int b    = tok0 >> 10;           // 8 | 1024, so one batch per block
    const int t    = threadIdx.x;          // float4 lane 0..191

    const float4 me = __ldg(reinterpret_cast<const float4*>(mask_emb) + t);

    int infos[TOK_PER_BLK];
    #pragma unroll
    for (int it = 0; it < TOK_PER_BLK; ++it)
        infos[it] = __ldg(&g_info[tok0 + it]);

    float4* wm_base = reinterpret_cast<float4*>(out + OFF_WITHMASK);
    float4* be_base = reinterpret_cast<float4*>(out + OFF_BOOL);
    float4* up_base = reinterpret_cast<float4*>(out + OFF_UNMP);
    const float4* patch4 = reinterpret_cast<const float4*>(patch);

    #pragma unroll
    for (int it = 0; it < TOK_PER_BLK; ++it) {
        const int tok = tok0 + it;
        const int info = infos[it];
        const size_t row = (size_t)tok * D4;

        const float bv = (info < 0) ? 1.0f : 0.0f;
        be_base[row + t] = make_float4(bv, bv, bv, bv);

        if (info < 0) {
            wm_base[row + t] = me;
        } else {
            float4 pch = __ldg(patch4 + row + t);
            wm_base[row + t] = pch;
            up_base[((size_t)b * NUNM + info) * D4 + t] = pch;
        }
    }
}

extern "C" void kernel_launch(void* const* d_in, const int* in_sizes, int n_in,
                              void* d_out, int out_size)
{
    const float* patch    = (const float*)d_in[0];  // (B, N, D) f32
    const float* noise    = (const float*)d_in[1];  // (B, N)    f32
    const float* mask_emb = (const float*)d_in[2];  // (D,)      f32
    float* out = (float*)d_out;

    mask_sort_kernel<<<BB, 1024>>>(noise, out);
    mask_scatter_kernel<<<BB * NN / TOK_PER_BLK, 192>>>(patch, mask_emb, out);
}